// round 4
// baseline (speedup 1.0000x reference)
#include <cuda_runtime.h>
#include <cuda_bf16.h>
#include <cstdint>

// Inputs (metadata order):
//   d_in[0] = x      float32 [262144]  (1 MB -> fully resident in cluster DSMEM)
//   d_in[1] = A_vals float32 [NNZ]     (streamed once)
//   d_in[2] = A_rows int32   [NNZ]     (streamed once)
//   d_in[3] = A_cols int32   [NNZ]     (streamed once)
// Output: float32 [262144]
//
// Strategy: cluster of 8 CTAs, each holding a 128KB slice of x in dynamic smem.
// Gathers become mapa + ld.shared::cluster (4B DSMEM reads, no L2 sector
// amplification). Streams + atomic scatter remain at L2, which was the binder.

#define CLUSTER_N    8
#define SLICE_ELEMS  32768          // 262144 / 8
#define SLICE_BYTES  (SLICE_ELEMS * 4)
#define CTA_THREADS  1024
#define GRID_CTAS    144            // 18 clusters * 8, <= 148 SMs

__device__ __forceinline__ uint32_t smem_u32(const void* p) {
    uint32_t a;
    asm("{ .reg .u64 t; cvta.to.shared.u64 t, %1; cvt.u32.u64 %0, t; }"
        : "=r"(a) : "l"(p));
    return a;
}

// Gather x[col] from the cluster-distributed copy.
__device__ __forceinline__ float dsmem_gather(uint32_t smem_base, int col) {
    uint32_t uc    = (uint32_t)col;
    uint32_t rank  = uc >> 15;                     // which CTA holds it
    uint32_t laddr = smem_base + ((uc & 32767u) << 2);
    uint32_t raddr;
    asm("mapa.shared::cluster.u32 %0, %1, %2;" : "=r"(raddr) : "r"(laddr), "r"(rank));
    float v;
    asm volatile("ld.shared::cluster.f32 %0, [%1];" : "=f"(v) : "r"(raddr));
    return v;
}

__global__ void __launch_bounds__(CTA_THREADS, 1) __cluster_dims__(CLUSTER_N, 1, 1)
coo_spmv_cluster_kernel(
    const float*  __restrict__ x,
    const float4* __restrict__ vals4,
    const int4*   __restrict__ rows4,
    const int4*   __restrict__ cols4,
    float*        __restrict__ out,
    int nnz4, int nnz)
{
    extern __shared__ float xs[];   // SLICE_ELEMS floats = this CTA's slice of x

    uint32_t rank;
    asm("mov.u32 %0, %%cluster_ctarank;" : "=r"(rank));

    // Stage this CTA's slice of x into smem (coalesced float4).
    {
        const float4* src = (const float4*)(x + rank * SLICE_ELEMS);
        float4* dst = (float4*)xs;
        #pragma unroll
        for (int j = 0; j < SLICE_ELEMS / 4 / CTA_THREADS; j++)
            dst[threadIdx.x + j * CTA_THREADS] = src[threadIdx.x + j * CTA_THREADS];
    }
    // All slices visible cluster-wide before any gather.
    asm volatile("barrier.cluster.arrive.aligned;" ::: "memory");
    asm volatile("barrier.cluster.wait.aligned;"   ::: "memory");

    const uint32_t sbase = smem_u32(xs);

    const int tid    = blockIdx.x * CTA_THREADS + threadIdx.x;
    const int stride = gridDim.x * CTA_THREADS;

    for (int i = tid; i < nnz4; i += stride) {
        float4 v = __ldg(&vals4[i]);
        int4   r = __ldg(&rows4[i]);
        int4   c = __ldg(&cols4[i]);

        float x0 = dsmem_gather(sbase, c.x);
        float x1 = dsmem_gather(sbase, c.y);
        float x2 = dsmem_gather(sbase, c.z);
        float x3 = dsmem_gather(sbase, c.w);

        atomicAdd(&out[r.x], v.x * x0);
        atomicAdd(&out[r.y], v.y * x1);
        atomicAdd(&out[r.z], v.z * x2);
        atomicAdd(&out[r.w], v.w * x3);
    }

    // Scalar tail (nnz % 4) — empty for this shape but kept correct.
    for (int i = nnz4 * 4 + tid; i < nnz; i += stride) {
        const float* vs = (const float*)vals4;
        const int*   rs = (const int*)rows4;
        const int*   cs = (const int*)cols4;
        atomicAdd(&out[rs[i]], vs[i] * dsmem_gather(sbase, cs[i]));
    }

    // Keep smem alive until all peers are done gathering.
    asm volatile("barrier.cluster.arrive.aligned;" ::: "memory");
    asm volatile("barrier.cluster.wait.aligned;"   ::: "memory");
}

extern "C" void kernel_launch(void* const* d_in, const int* in_sizes, int n_in,
                              void* d_out, int out_size) {
    const float* x    = (const float*)d_in[0];
    const float* vals = (const float*)d_in[1];
    const int*   rows = (const int*)d_in[2];
    const int*   cols = (const int*)d_in[3];
    float* out = (float*)d_out;

    const int nnz  = in_sizes[1];
    const int nnz4 = nnz / 4;

    // Opt-in to 128KB dynamic smem (idempotent; cheap).
    cudaFuncSetAttribute(coo_spmv_cluster_kernel,
                         cudaFuncAttributeMaxDynamicSharedMemorySize, SLICE_BYTES);

    // Zero-init output (harness poisons it).
    cudaMemsetAsync(out, 0, (size_t)out_size * sizeof(float), 0);

    coo_spmv_cluster_kernel<<<GRID_CTAS, CTA_THREADS, SLICE_BYTES>>>(
        x, (const float4*)vals, (const int4*)rows, (const int4*)cols,
        out, nnz4, nnz);
}

// round 5
// speedup vs baseline: 2.8299x; 2.8299x over previous
#include <cuda_runtime.h>
#include <cuda_bf16.h>
#include <cstdint>

// Inputs (metadata order):
//   d_in[0] = x      float32 [262144]  (1 MB, random-gathered; L2-resident, let it own L1)
//   d_in[1] = A_vals float32 [NNZ]     (streamed once -> L2-only via ld.cg)
//   d_in[2] = A_rows int32   [NNZ]     (streamed once -> L2-only via ld.cg)
//   d_in[3] = A_cols int32   [NNZ]     (streamed once -> L2-only via ld.cg)
// Output: float32 [262144]
//
// R1 structure (fastest so far) + .cg streams so the index/value stream does
// not allocate L1 lines, leaving L1 capacity to the x gather working set.

__device__ __forceinline__ float4 ldcg_f4(const float4* p) {
    float4 v;
    asm volatile("ld.global.cg.v4.f32 {%0,%1,%2,%3}, [%4];"
                 : "=f"(v.x), "=f"(v.y), "=f"(v.z), "=f"(v.w) : "l"(p));
    return v;
}
__device__ __forceinline__ int4 ldcg_i4(const int4* p) {
    int4 v;
    asm volatile("ld.global.cg.v4.b32 {%0,%1,%2,%3}, [%4];"
                 : "=r"(v.x), "=r"(v.y), "=r"(v.z), "=r"(v.w) : "l"(p));
    return v;
}

__global__ void __launch_bounds__(256) coo_spmv_kernel(
    const float*  __restrict__ x,
    const float4* __restrict__ vals4,
    const int4*   __restrict__ rows4,
    const int4*   __restrict__ cols4,
    float*        __restrict__ out,
    int nnz4)
{
    int i = blockIdx.x * blockDim.x + threadIdx.x;
    if (i >= nnz4) return;

    // Three independent 16B streaming loads (L2-only, no L1 pollution).
    float4 v = ldcg_f4(&vals4[i]);
    int4   r = ldcg_i4(&rows4[i]);
    int4   c = ldcg_i4(&cols4[i]);

    // Random gathers from x: default allocating nc-load; x owns L1 now.
    float x0 = __ldg(&x[c.x]);
    float x1 = __ldg(&x[c.y]);
    float x2 = __ldg(&x[c.z]);
    float x3 = __ldg(&x[c.w]);

    // Scatter-add: return value unused -> RED.E.ADD.F32 at L2.
    atomicAdd(&out[r.x], v.x * x0);
    atomicAdd(&out[r.y], v.y * x1);
    atomicAdd(&out[r.z], v.z * x2);
    atomicAdd(&out[r.w], v.w * x3);
}

// Tail handler for nnz not divisible by 4 (unused for this shape, kept safe).
__global__ void coo_spmv_tail_kernel(
    const float* __restrict__ x,
    const float* __restrict__ vals,
    const int*   __restrict__ rows,
    const int*   __restrict__ cols,
    float*       __restrict__ out,
    int start, int nnz)
{
    int i = start + blockIdx.x * blockDim.x + threadIdx.x;
    if (i < nnz) {
        atomicAdd(&out[rows[i]], vals[i] * __ldg(&x[cols[i]]));
    }
}

extern "C" void kernel_launch(void* const* d_in, const int* in_sizes, int n_in,
                              void* d_out, int out_size) {
    const float* x    = (const float*)d_in[0];
    const float* vals = (const float*)d_in[1];
    const int*   rows = (const int*)d_in[2];
    const int*   cols = (const int*)d_in[3];
    float* out = (float*)d_out;

    const int nnz = in_sizes[1];

    // Zero-init output (harness poisons it). Memset node: cheaper than a kernel.
    cudaMemsetAsync(out, 0, (size_t)out_size * sizeof(float), 0);

    // Main vectorized COO pass: 4 nnz per thread (R1-winning shape).
    int nnz4 = nnz / 4;
    if (nnz4 > 0) {
        int threads = 256;
        int blocks = (nnz4 + threads - 1) / threads;
        coo_spmv_kernel<<<blocks, threads>>>(
            x, (const float4*)vals, (const int4*)rows, (const int4*)cols, out, nnz4);
    }

    // Tail (nnz % 4): empty for this shape, guarded on host (no launch cost).
    int tail_start = nnz4 * 4;
    int tail = nnz - tail_start;
    if (tail > 0) {
        coo_spmv_tail_kernel<<<(tail + 255) / 256, 256>>>(
            x, vals, rows, cols, out, tail_start, nnz);
    }
}